// round 1
// baseline (speedup 1.0000x reference)
#include <cuda_runtime.h>
#include <math.h>

// Model dims
#define BT   2
#define TT   2048
#define NTOK 4096      // B*T
#define DM   512
#define NH   8
#define HSZ  64
#define FFD  2048
#define NL   6
#define VOC  32000

// Scratch (device globals: allocation-free per harness rules)
__device__ float g_x [NTOK * DM];
__device__ float g_h [NTOK * DM];
__device__ float g_q [NTOK * DM];
__device__ float g_k [NTOK * DM];
__device__ float g_v [NTOK * DM];
__device__ float g_a [NTOK * DM];
__device__ float g_ff[NTOK * FFD];
__device__ float g_red[2];
// Fallback logits buffer in case d_out does not hold the full logits matrix
__device__ float g_logits_fb[(size_t)NTOK * VOC];

// ---------------------------------------------------------------------------
// Reduction helpers
// ---------------------------------------------------------------------------
__device__ __forceinline__ float warpSum(float v) {
#pragma unroll
    for (int o = 16; o > 0; o >>= 1) v += __shfl_xor_sync(0xffffffffu, v, o);
    return v;
}
__device__ __forceinline__ float warpMax(float v) {
#pragma unroll
    for (int o = 16; o > 0; o >>= 1) v = fmaxf(v, __shfl_xor_sync(0xffffffffu, v, o));
    return v;
}

// ---------------------------------------------------------------------------
// Embedding: x[n,:] = tok_emb[tokens[n],:] + pos_emb[n % T,:]
// ---------------------------------------------------------------------------
__global__ void embed_kernel(const int* __restrict__ toks,
                             const float* __restrict__ temb,
                             const float* __restrict__ pemb,
                             float* __restrict__ x) {
    int i = blockIdx.x * blockDim.x + threadIdx.x;   // over NTOK*DM/4 float4s
    if (i >= NTOK * DM / 4) return;
    int n  = i / (DM / 4);
    int c  = i % (DM / 4);
    int tk = toks[n];
    int t  = n % TT;
    float4 a = ((const float4*)temb)[(size_t)tk * (DM / 4) + c];
    float4 p = ((const float4*)pemb)[(size_t)t  * (DM / 4) + c];
    float4 r;
    r.x = a.x + p.x; r.y = a.y + p.y; r.z = a.z + p.z; r.w = a.w + p.w;
    ((float4*)x)[i] = r;
}

// ---------------------------------------------------------------------------
// LayerNorm: one block (128 threads) per row, D=512 -> 1 float4 per thread
// ---------------------------------------------------------------------------
__global__ void ln_kernel(const float* __restrict__ in, float* __restrict__ out,
                          const float* __restrict__ gamma, const float* __restrict__ beta) {
    int row = blockIdx.x;
    int tid = threadIdx.x;        // 128
    const float4 v4 = ((const float4*)(in + (size_t)row * DM))[tid];
    float s  = v4.x + v4.y + v4.z + v4.w;
    float s2 = v4.x * v4.x + v4.y * v4.y + v4.z * v4.z + v4.w * v4.w;

    __shared__ float rs[4], rs2[4];
    int warp = tid >> 5, lane = tid & 31;
    s = warpSum(s); s2 = warpSum(s2);
    if (lane == 0) { rs[warp] = s; rs2[warp] = s2; }
    __syncthreads();
    float ts = 0.f, ts2 = 0.f;
#pragma unroll
    for (int w = 0; w < 4; w++) { ts += rs[w]; ts2 += rs2[w]; }
    float mean = ts * (1.0f / DM);
    float var  = ts2 * (1.0f / DM) - mean * mean;
    float rstd = rsqrtf(var + 1e-5f);

    float4 g4 = ((const float4*)gamma)[tid];
    float4 b4 = ((const float4*)beta)[tid];
    float4 o;
    o.x = (v4.x - mean) * rstd * g4.x + b4.x;
    o.y = (v4.y - mean) * rstd * g4.y + b4.y;
    o.z = (v4.z - mean) * rstd * g4.z + b4.z;
    o.w = (v4.w - mean) * rstd * g4.w + b4.w;
    ((float4*)(out + (size_t)row * DM))[tid] = o;
}

// ---------------------------------------------------------------------------
// Tiled SGEMM: C[M,N] = A[M,K] @ B[K,N]  (+bias, +residual, relu as flags)
// BM=BN=64, BK=16, 256 threads, 4x4 per thread. All dims multiples assumed.
// blockIdx.z applies strides bz (on B) and cz (on C) for per-head GEMMs.
// ---------------------------------------------------------------------------
template<int BIAS, int RES, int RELU>
__global__ void sgemm_kernel(const float* __restrict__ A, const float* __restrict__ B,
                             const float* __restrict__ bias, const float* __restrict__ res,
                             float* __restrict__ C,
                             int M, int N, int K, int lda, int ldb, int ldc,
                             long bz, long cz) {
    B += (long)blockIdx.z * bz;
    C += (long)blockIdx.z * cz;

    __shared__ float As[16][64];
    __shared__ float Bs[16][64];

    int tid = threadIdx.x;
    int rowBase = blockIdx.y * 64;
    int colBase = blockIdx.x * 64;
    int tx = tid & 15, ty = tid >> 4;

    // Load mapping
    int ar = tid >> 2;          // 0..63
    int ac = (tid & 3) * 4;     // 0,4,8,12
    int br = tid >> 4;          // 0..15
    int bc = (tid & 15) * 4;    // 0..60

    float acc[4][4];
#pragma unroll
    for (int i = 0; i < 4; i++)
#pragma unroll
        for (int j = 0; j < 4; j++) acc[i][j] = 0.f;

    for (int k0 = 0; k0 < K; k0 += 16) {
        float4 av = *(const float4*)(A + (size_t)(rowBase + ar) * lda + k0 + ac);
        float4 bv = *(const float4*)(B + (size_t)(k0 + br) * ldb + colBase + bc);
        As[ac + 0][ar] = av.x; As[ac + 1][ar] = av.y;
        As[ac + 2][ar] = av.z; As[ac + 3][ar] = av.w;
        *(float4*)&Bs[br][bc] = bv;
        __syncthreads();
#pragma unroll
        for (int kk = 0; kk < 16; kk++) {
            float a0 = As[kk][ty * 4 + 0];
            float a1 = As[kk][ty * 4 + 1];
            float a2 = As[kk][ty * 4 + 2];
            float a3 = As[kk][ty * 4 + 3];
            float4 b4 = *(float4*)&Bs[kk][tx * 4];
            acc[0][0] += a0 * b4.x; acc[0][1] += a0 * b4.y; acc[0][2] += a0 * b4.z; acc[0][3] += a0 * b4.w;
            acc[1][0] += a1 * b4.x; acc[1][1] += a1 * b4.y; acc[1][2] += a1 * b4.z; acc[1][3] += a1 * b4.w;
            acc[2][0] += a2 * b4.x; acc[2][1] += a2 * b4.y; acc[2][2] += a2 * b4.z; acc[2][3] += a2 * b4.w;
            acc[3][0] += a3 * b4.x; acc[3][1] += a3 * b4.y; acc[3][2] += a3 * b4.z; acc[3][3] += a3 * b4.w;
        }
        __syncthreads();
    }

    float4 bias4 = make_float4(0.f, 0.f, 0.f, 0.f);
    if (BIAS) bias4 = *(const float4*)(bias + colBase + tx * 4);

#pragma unroll
    for (int i = 0; i < 4; i++) {
        size_t off = (size_t)(rowBase + ty * 4 + i) * ldc + colBase + tx * 4;
        float4 o = make_float4(acc[i][0], acc[i][1], acc[i][2], acc[i][3]);
        if (BIAS) { o.x += bias4.x; o.y += bias4.y; o.z += bias4.z; o.w += bias4.w; }
        if (RES)  {
            float4 r4 = *(const float4*)(res + off);
            o.x += r4.x; o.y += r4.y; o.z += r4.z; o.w += r4.w;
        }
        if (RELU) {
            o.x = fmaxf(o.x, 0.f); o.y = fmaxf(o.y, 0.f);
            o.z = fmaxf(o.z, 0.f); o.w = fmaxf(o.w, 0.f);
        }
        *(float4*)(C + off) = o;
    }
}

// ---------------------------------------------------------------------------
// Causal attention, one block per (query t, head, batch). 128 threads.
// q,k,v,out layout: [NTOK, D] with column = head*64 + hs
// ---------------------------------------------------------------------------
__global__ void attn_kernel(const float* __restrict__ q, const float* __restrict__ k,
                            const float* __restrict__ v, float* __restrict__ out) {
    int t = blockIdx.x, head = blockIdx.y, b = blockIdx.z;
    int n = b * TT + t;
    int tid = threadIdx.x;    // 128
    int warp = tid >> 5, lane = tid & 31;

    __shared__ float sq[HSZ];
    __shared__ float sc[TT];
    __shared__ float red[4];

    if (tid < HSZ) sq[tid] = q[(size_t)n * DM + head * HSZ + tid];
    __syncthreads();

    // scores
    float lmax = -INFINITY;
    for (int j = tid; j <= t; j += 128) {
        const float* kr = k + (size_t)(b * TT + j) * DM + head * HSZ;
        float acc = 0.f;
#pragma unroll
        for (int d = 0; d < HSZ; d++) acc += sq[d] * kr[d];
        acc *= 0.125f;   // HS^-0.5
        sc[j] = acc;
        lmax = fmaxf(lmax, acc);
    }
    lmax = warpMax(lmax);
    if (lane == 0) red[warp] = lmax;
    __syncthreads();
    float gmax = fmaxf(fmaxf(red[0], red[1]), fmaxf(red[2], red[3]));
    __syncthreads();

    // exp + sum
    float lsum = 0.f;
    for (int j = tid; j <= t; j += 128) {
        float e = expf(sc[j] - gmax);
        sc[j] = e;
        lsum += e;
    }
    lsum = warpSum(lsum);
    if (lane == 0) red[warp] = lsum;
    __syncthreads();
    float gsum = red[0] + red[1] + red[2] + red[3];
    __syncthreads();

    // weighted sum of V (64 active threads, one per hs)
    if (tid < HSZ) {
        float acc = 0.f;
        const float* vb = v + (size_t)(b * TT) * DM + head * HSZ + tid;
        for (int j = 0; j <= t; j++) {
            acc += sc[j] * vb[(size_t)j * DM];
        }
        out[(size_t)n * DM + head * HSZ + tid] = acc / gsum;
    }
}

// ---------------------------------------------------------------------------
// Loss: per-row log-softmax NLL, masked (target != 0), accumulated atomically
// ---------------------------------------------------------------------------
__global__ void zero_kernel(float* red) { red[0] = 0.f; red[1] = 0.f; }

__global__ void loss_kernel(const float* __restrict__ logits, const int* __restrict__ tgt,
                            float* __restrict__ red) {
    int r = blockIdx.x;
    int tid = threadIdx.x;   // 256
    int warp = tid >> 5, lane = tid & 31;
    const float* row = logits + (size_t)r * VOC;
    __shared__ float rbuf[8];

    float lmax = -INFINITY;
    for (int c = tid; c < VOC; c += 256) lmax = fmaxf(lmax, row[c]);
    lmax = warpMax(lmax);
    if (lane == 0) rbuf[warp] = lmax;
    __syncthreads();
    float gmax = -INFINITY;
#pragma unroll
    for (int w = 0; w < 8; w++) gmax = fmaxf(gmax, rbuf[w]);
    __syncthreads();

    float lsum = 0.f;
    for (int c = tid; c < VOC; c += 256) lsum += expf(row[c] - gmax);
    lsum = warpSum(lsum);
    if (lane == 0) rbuf[warp] = lsum;
    __syncthreads();
    if (tid == 0) {
        float gsum = 0.f;
#pragma unroll
        for (int w = 0; w < 8; w++) gsum += rbuf[w];
        int tg = tgt[r];
        float lp = row[tg] - gmax - logf(gsum);
        float m = (tg != 0) ? 1.0f : 0.0f;
        atomicAdd(&red[0], -lp * m);
        atomicAdd(&red[1], m);
    }
}

__global__ void finalize_kernel(const float* __restrict__ red, float* __restrict__ outp) {
    outp[0] = red[0] / red[1];
}

// ---------------------------------------------------------------------------
// Host driver
// ---------------------------------------------------------------------------
extern "C" void kernel_launch(void* const* d_in, const int* in_sizes, int n_in,
                              void* d_out, int out_size) {
    const int*   toks = (const int*)d_in[0];
    const int*   tgts = (const int*)d_in[1];
    const float* temb = (const float*)d_in[2];
    const float* pemb = (const float*)d_in[3];
    const float* Wq   = (const float*)d_in[4];
    const float* Wk   = (const float*)d_in[5];
    const float* Wv   = (const float*)d_in[6];
    const float* Wo   = (const float*)d_in[7];
    const float* bo   = (const float*)d_in[8];
    const float* ln1g = (const float*)d_in[9];
    const float* ln1b = (const float*)d_in[10];
    const float* ln2g = (const float*)d_in[11];
    const float* ln2b = (const float*)d_in[12];
    const float* W1   = (const float*)d_in[13];
    const float* b1   = (const float*)d_in[14];
    const float* W2   = (const float*)d_in[15];
    const float* b2   = (const float*)d_in[16];
    const float* lnfg = (const float*)d_in[17];
    const float* lnfb = (const float*)d_in[18];
    const float* Wout = (const float*)d_in[19];
    const float* bout = (const float*)d_in[20];

    float *x, *h, *q, *k, *v, *a, *ff, *red, *lfb;
    cudaGetSymbolAddress((void**)&x,   g_x);
    cudaGetSymbolAddress((void**)&h,   g_h);
    cudaGetSymbolAddress((void**)&q,   g_q);
    cudaGetSymbolAddress((void**)&k,   g_k);
    cudaGetSymbolAddress((void**)&v,   g_v);
    cudaGetSymbolAddress((void**)&a,   g_a);
    cudaGetSymbolAddress((void**)&ff,  g_ff);
    cudaGetSymbolAddress((void**)&red, g_red);
    cudaGetSymbolAddress((void**)&lfb, g_logits_fb);

    embed_kernel<<<(NTOK * DM / 4 + 255) / 256, 256>>>(toks, temb, pemb, x);

    for (int l = 0; l < NL; l++) {
        ln_kernel<<<NTOK, 128>>>(x, h, ln1g + l * DM, ln1b + l * DM);

        // Per-head QKV projections: grid.z = head
        sgemm_kernel<0, 0, 0><<<dim3(1, NTOK / 64, NH), 256>>>(
            h, Wq + (size_t)l * NH * DM * HSZ, nullptr, nullptr, q,
            NTOK, HSZ, DM, DM, HSZ, DM, (long)DM * HSZ, HSZ);
        sgemm_kernel<0, 0, 0><<<dim3(1, NTOK / 64, NH), 256>>>(
            h, Wk + (size_t)l * NH * DM * HSZ, nullptr, nullptr, k,
            NTOK, HSZ, DM, DM, HSZ, DM, (long)DM * HSZ, HSZ);
        sgemm_kernel<0, 0, 0><<<dim3(1, NTOK / 64, NH), 256>>>(
            h, Wv + (size_t)l * NH * DM * HSZ, nullptr, nullptr, v,
            NTOK, HSZ, DM, DM, HSZ, DM, (long)DM * HSZ, HSZ);

        attn_kernel<<<dim3(TT, NH, BT), 128>>>(q, k, v, a);

        // Output projection + bias + residual -> x
        sgemm_kernel<1, 1, 0><<<dim3(DM / 64, NTOK / 64, 1), 256>>>(
            a, Wo + (size_t)l * DM * DM, bo + l * DM, x, x,
            NTOK, DM, DM, DM, DM, DM, 0, 0);

        ln_kernel<<<NTOK, 128>>>(x, h, ln2g + l * DM, ln2b + l * DM);

        // FF1 + bias + relu
        sgemm_kernel<1, 0, 1><<<dim3(FFD / 64, NTOK / 64, 1), 256>>>(
            h, W1 + (size_t)l * DM * FFD, b1 + (size_t)l * FFD, nullptr, ff,
            NTOK, FFD, DM, DM, FFD, FFD, 0, 0);
        // FF2 + bias + residual -> x
        sgemm_kernel<1, 1, 0><<<dim3(DM / 64, NTOK / 64, 1), 256>>>(
            ff, W2 + (size_t)l * FFD * DM, b2 + l * DM, x, x,
            NTOK, DM, FFD, FFD, DM, DM, 0, 0);
    }

    ln_kernel<<<NTOK, 128>>>(x, h, lnfg, lnfb);

    const long logitsElems = (long)NTOK * VOC;
    float* logits = ((long)out_size >= logitsElems) ? (float*)d_out : lfb;

    sgemm_kernel<1, 0, 0><<<dim3(VOC / 64, NTOK / 64, 1), 256>>>(
        h, Wout, bout, nullptr, logits,
        NTOK, VOC, DM, DM, VOC, VOC, 0, 0);

    if ((long)out_size != logitsElems) {
        zero_kernel<<<1, 1>>>(red);
        loss_kernel<<<NTOK, 256>>>(logits, tgts, red);
        float* lossOut;
        if ((long)out_size > logitsElems)
            lossOut = (float*)d_out + logitsElems;
        else
            lossOut = (float*)d_out + (out_size - 1);
        finalize_kernel<<<1, 1>>>(red, lossOut);
    }
}

// round 4
// speedup vs baseline: 6.2356x; 6.2356x over previous
#include <cuda_runtime.h>
#include <math.h>
#include <stdint.h>

// Model dims
#define BT   2
#define TT   2048
#define NTOK 4096
#define DM   512
#define NH   8
#define HSZ  64
#define FFD  2048
#define NL   6
#define VOC  32000

// Scratch
__device__ float g_x [NTOK * DM];
__device__ float g_h [NTOK * DM];
__device__ float g_q [NTOK * DM];
__device__ float g_k [NTOK * DM];
__device__ float g_v [NTOK * DM];
__device__ float g_a [NTOK * DM];
__device__ float g_ff[NTOK * FFD];
__device__ float g_red[2];
__device__ float g_logits_fb[(size_t)NTOK * VOC];

// ---------------------------------------------------------------------------
__device__ __forceinline__ float warpSum(float v) {
#pragma unroll
    for (int o = 16; o > 0; o >>= 1) v += __shfl_xor_sync(0xffffffffu, v, o);
    return v;
}
__device__ __forceinline__ float warpMax(float v) {
#pragma unroll
    for (int o = 16; o > 0; o >>= 1) v = fmaxf(v, __shfl_xor_sync(0xffffffffu, v, o));
    return v;
}

// ---------------------------------------------------------------------------
__global__ void embed_kernel(const int* __restrict__ toks,
                             const float* __restrict__ temb,
                             const float* __restrict__ pemb,
                             float* __restrict__ x) {
    int i = blockIdx.x * blockDim.x + threadIdx.x;
    if (i >= NTOK * DM / 4) return;
    int n  = i / (DM / 4);
    int c  = i % (DM / 4);
    int tk = toks[n];
    int t  = n % TT;
    float4 a = ((const float4*)temb)[(size_t)tk * (DM / 4) + c];
    float4 p = ((const float4*)pemb)[(size_t)t  * (DM / 4) + c];
    float4 r;
    r.x = a.x + p.x; r.y = a.y + p.y; r.z = a.z + p.z; r.w = a.w + p.w;
    ((float4*)x)[i] = r;
}

// ---------------------------------------------------------------------------
__global__ void ln_kernel(const float* __restrict__ in, float* __restrict__ out,
                          const float* __restrict__ gamma, const float* __restrict__ beta) {
    int row = blockIdx.x;
    int tid = threadIdx.x;
    const float4 v4 = ((const float4*)(in + (size_t)row * DM))[tid];
    float s  = v4.x + v4.y + v4.z + v4.w;
    float s2 = v4.x * v4.x + v4.y * v4.y + v4.z * v4.z + v4.w * v4.w;

    __shared__ float rs[4], rs2[4];
    int warp = tid >> 5, lane = tid & 31;
    s = warpSum(s); s2 = warpSum(s2);
    if (lane == 0) { rs[warp] = s; rs2[warp] = s2; }
    __syncthreads();
    float ts = 0.f, ts2 = 0.f;
#pragma unroll
    for (int w = 0; w < 4; w++) { ts += rs[w]; ts2 += rs2[w]; }
    float mean = ts * (1.0f / DM);
    float var  = ts2 * (1.0f / DM) - mean * mean;
    float rstd = rsqrtf(var + 1e-5f);

    float4 g4 = ((const float4*)gamma)[tid];
    float4 b4 = ((const float4*)beta)[tid];
    float4 o;
    o.x = (v4.x - mean) * rstd * g4.x + b4.x;
    o.y = (v4.y - mean) * rstd * g4.y + b4.y;
    o.z = (v4.z - mean) * rstd * g4.z + b4.z;
    o.w = (v4.w - mean) * rstd * g4.w + b4.w;
    ((float4*)(out + (size_t)row * DM))[tid] = o;
}

// ---------------------------------------------------------------------------
// 3xTF32 tensor-core GEMM (fp32-accurate): C[M,N] = A[M,K] @ B[K,N]
// BM=128, BN=64, BK=32. 256 threads = 8 warps (4 m x 2 n). Warp tile 32x32.
// Double-buffered SMEM via cp.async. Operands split hi/lo in registers:
//   C += Ah*Bh + Ah*Bl + Al*Bh   (error ~2^-21, fp32-equivalent)
// ---------------------------------------------------------------------------
#define ASTR 36
#define BSTR 72
#define ABUF (128 * ASTR)
#define BBUF (32 * BSTR)
#define GEMM_SMEM ((2 * (ABUF + BBUF)) * 4)  // 55296 bytes

__device__ __forceinline__ void cpa16(uint32_t s, const void* g) {
    asm volatile("cp.async.cg.shared.global [%0], [%1], 16;\n" :: "r"(s), "l"(g));
}

__device__ __forceinline__ unsigned f2tf(float x) {
    unsigned r;
    asm("cvt.rna.tf32.f32 %0, %1;\n" : "=r"(r) : "f"(x));
    return r;
}

__device__ __forceinline__ void mma_u(float (&c)[4], const unsigned (&A)[4], const unsigned (&B)[2]) {
    asm volatile(
        "mma.sync.aligned.m16n8k8.row.col.f32.tf32.tf32.f32 "
        "{%0,%1,%2,%3}, {%4,%5,%6,%7}, {%8,%9}, {%0,%1,%2,%3};\n"
        : "+f"(c[0]), "+f"(c[1]), "+f"(c[2]), "+f"(c[3])
        : "r"(A[0]), "r"(A[1]), "r"(A[2]), "r"(A[3]), "r"(B[0]), "r"(B[1]));
}

template<int BIAS, int RES, int RELU>
__global__ void __launch_bounds__(256)
tgemm(const float* __restrict__ A, const float* __restrict__ B,
      const float* __restrict__ bias, const float* __restrict__ res,
      float* __restrict__ C,
      int M, int N, int K, int lda, int ldb, int ldc, long bz, long cz) {
    extern __shared__ float sm[];
    float* sA = sm;
    float* sB = sm + 2 * ABUF;

    B += (long)blockIdx.z * bz;
    C += (long)blockIdx.z * cz;

    int tid = threadIdx.x;
    int rowBase = blockIdx.y * 128;
    int colBase = blockIdx.x * 64;

    uint32_t sAaddr = (uint32_t)__cvta_generic_to_shared(sA);
    uint32_t sBaddr = (uint32_t)__cvta_generic_to_shared(sB);

    int ntiles = K >> 5;

    {
#pragma unroll
        for (int i = 0; i < 4; i++) {
            int idx = tid + i * 256;
            int r = idx >> 3, c = (idx & 7) * 4;
            cpa16(sAaddr + (uint32_t)(r * ASTR + c) * 4,
                  A + (size_t)(rowBase + r) * lda + c);
        }
#pragma unroll
        for (int i = 0; i < 2; i++) {
            int idx = tid + i * 256;
            int r = idx >> 4, c = (idx & 15) * 4;
            cpa16(sBaddr + (uint32_t)(r * BSTR + c) * 4,
                  B + (size_t)r * ldb + colBase + c);
        }
        asm volatile("cp.async.commit_group;\n");
    }

    float acc[2][4][4] = {};
    int lane = tid & 31, warp = tid >> 5;
    int wm = warp >> 1, wn = warp & 1;
    int g = lane >> 2, tg = lane & 3;

    for (int t = 0; t < ntiles; t++) {
        asm volatile("cp.async.wait_group 0;\n");
        __syncthreads();
        int cur = t & 1, nxt = cur ^ 1;

        if (t + 1 < ntiles) {
            int k0 = (t + 1) << 5;
#pragma unroll
            for (int i = 0; i < 4; i++) {
                int idx = tid + i * 256;
                int r = idx >> 3, c = (idx & 7) * 4;
                cpa16(sAaddr + (uint32_t)(nxt * ABUF + r * ASTR + c) * 4,
                      A + (size_t)(rowBase + r) * lda + k0 + c);
            }
#pragma unroll
            for (int i = 0; i < 2; i++) {
                int idx = tid + i * 256;
                int r = idx >> 4, c = (idx & 15) * 4;
                cpa16(sBaddr + (uint32_t)(nxt * BBUF + r * BSTR + c) * 4,
                      B + (size_t)(k0 + r) * ldb + colBase + c);
            }
            asm volatile("cp.async.commit_group;\n");
        }

        const float* cA = sA + cur * ABUF;
        const float* cB = sB + cur * BBUF;

#pragma unroll
        for (int kk = 0; kk < 4; kk++) {
            float a[2][4], b[4][2];
#pragma unroll
            for (int mt = 0; mt < 2; mt++) {
                int mb = wm * 32 + mt * 16;
                a[mt][0] = cA[(mb + g)     * ASTR + kk * 8 + tg];
                a[mt][1] = cA[(mb + 8 + g) * ASTR + kk * 8 + tg];
                a[mt][2] = cA[(mb + g)     * ASTR + kk * 8 + 4 + tg];
                a[mt][3] = cA[(mb + 8 + g) * ASTR + kk * 8 + 4 + tg];
            }
#pragma unroll
            for (int nt = 0; nt < 4; nt++) {
                int nb = wn * 32 + nt * 8;
                b[nt][0] = cB[(kk * 8 + tg)     * BSTR + nb + g];
                b[nt][1] = cB[(kk * 8 + 4 + tg) * BSTR + nb + g];
            }

            // hi/lo split (3xTF32)
            unsigned ah[2][4], al[2][4], bh[4][2], bl[4][2];
#pragma unroll
            for (int mt = 0; mt < 2; mt++)
#pragma unroll
                for (int i = 0; i < 4; i++) {
                    unsigned h = f2tf(a[mt][i]);
                    ah[mt][i] = h;
                    al[mt][i] = f2tf(a[mt][i] - __uint_as_float(h));
                }
#pragma unroll
            for (int nt = 0; nt < 4; nt++)
#pragma unroll
                for (int i = 0; i < 2; i++) {
                    unsigned h = f2tf(b[nt][i]);
                    bh[nt][i] = h;
                    bl[nt][i] = f2tf(b[nt][i] - __uint_as_float(h));
                }

#pragma unroll
            for (int mt = 0; mt < 2; mt++)
#pragma unroll
                for (int nt = 0; nt < 4; nt++) {
                    mma_u(acc[mt][nt], al[mt], bh[nt]);
                    mma_u(acc[mt][nt], ah[mt], bl[nt]);
                    mma_u(acc[mt][nt], ah[mt], bh[nt]);
                }
        }
        __syncthreads();
    }

#pragma unroll
    for (int mt = 0; mt < 2; mt++) {
#pragma unroll
        for (int nt = 0; nt < 4; nt++) {
            int r0 = rowBase + wm * 32 + mt * 16 + g;
            int c0 = colBase + wn * 32 + nt * 8 + 2 * tg;
            float bx = 0.f, by = 0.f;
            if (BIAS) { bx = bias[c0]; by = bias[c0 + 1]; }
            size_t o0 = (size_t)r0 * ldc + c0;
            size_t o1 = (size_t)(r0 + 8) * ldc + c0;
            float v0 = acc[mt][nt][0] + bx;
            float v1 = acc[mt][nt][1] + by;
            float v2 = acc[mt][nt][2] + bx;
            float v3 = acc[mt][nt][3] + by;
            if (RES) {
                v0 += res[o0]; v1 += res[o0 + 1];
                v2 += res[o1]; v3 += res[o1 + 1];
            }
            if (RELU) {
                v0 = fmaxf(v0, 0.f); v1 = fmaxf(v1, 0.f);
                v2 = fmaxf(v2, 0.f); v3 = fmaxf(v3, 0.f);
            }
            C[o0] = v0; C[o0 + 1] = v1;
            C[o1] = v2; C[o1 + 1] = v3;
        }
    }
}

// ---------------------------------------------------------------------------
// Flash-style causal attention (fp32), 64 queries per block
// ---------------------------------------------------------------------------
#define QS 65
#define FLASH_SMEM ((4 * 64 * QS + 192) * 4)

__global__ void __launch_bounds__(256)
flash_attn(const float* __restrict__ q, const float* __restrict__ k,
           const float* __restrict__ v, float* __restrict__ out) {
    extern __shared__ float sm[];
    float* sQ = sm;
    float* sK = sQ + 64 * QS;
    float* sV = sK + 64 * QS;
    float* sS = sV + 64 * QS;
    float* sm_m = sS + 64 * QS;
    float* sm_l = sm_m + 64;
    float* sm_a = sm_l + 64;

    int qb = blockIdx.x * 64, h = blockIdx.y, b = blockIdx.z;
    int tid = threadIdx.x;
    int q0 = (tid >> 4) * 4;
    int d0 = (tid & 15) * 4;

    const float* qp = q + (size_t)(b * TT + qb) * DM + h * HSZ;
    for (int i = tid; i < 64 * 64; i += 256) {
        int r = i >> 6, c = i & 63;
        sQ[r * QS + c] = qp[(size_t)r * DM + c] * 0.125f;
    }
    if (tid < 64) { sm_m[tid] = -INFINITY; sm_l[tid] = 0.f; }

    float acc[4][4] = {};
    int nkt = qb >> 6;

    for (int kt = 0; kt <= nkt; kt++) {
        __syncthreads();
        const float* kp = k + (size_t)(b * TT + kt * 64) * DM + h * HSZ;
        const float* vp = v + (size_t)(b * TT + kt * 64) * DM + h * HSZ;
        for (int i = tid; i < 64 * 64; i += 256) {
            int r = i >> 6, c = i & 63;
            sK[r * QS + c] = kp[(size_t)r * DM + c];
            sV[r * QS + c] = vp[(size_t)r * DM + c];
        }
        __syncthreads();

        float s[4][4] = {};
#pragma unroll 8
        for (int d = 0; d < 64; d++) {
            float a0 = sQ[(q0 + 0) * QS + d];
            float a1 = sQ[(q0 + 1) * QS + d];
            float a2 = sQ[(q0 + 2) * QS + d];
            float a3 = sQ[(q0 + 3) * QS + d];
            float b0 = sK[(d0 + 0) * QS + d];
            float b1 = sK[(d0 + 1) * QS + d];
            float b2 = sK[(d0 + 2) * QS + d];
            float b3 = sK[(d0 + 3) * QS + d];
            s[0][0] += a0 * b0; s[0][1] += a0 * b1; s[0][2] += a0 * b2; s[0][3] += a0 * b3;
            s[1][0] += a1 * b0; s[1][1] += a1 * b1; s[1][2] += a1 * b2; s[1][3] += a1 * b3;
            s[2][0] += a2 * b0; s[2][1] += a2 * b1; s[2][2] += a2 * b2; s[2][3] += a2 * b3;
            s[3][0] += a3 * b0; s[3][1] += a3 * b1; s[3][2] += a3 * b2; s[3][3] += a3 * b3;
        }
        bool diag = (kt == nkt);
#pragma unroll
        for (int i = 0; i < 4; i++)
#pragma unroll
            for (int j = 0; j < 4; j++) {
                float sv = s[i][j];
                if (diag && (kt * 64 + d0 + j) > (qb + q0 + i)) sv = -INFINITY;
                sS[(q0 + i) * QS + d0 + j] = sv;
            }
        __syncthreads();

        if (tid < 64) {
            int r = tid;
            float m_old = sm_m[r];
            float mx = m_old;
#pragma unroll 8
            for (int j = 0; j < 64; j++) mx = fmaxf(mx, sS[r * QS + j]);
            float al = __expf(m_old - mx);
            float su = 0.f;
#pragma unroll 8
            for (int j = 0; j < 64; j++) {
                float p = __expf(sS[r * QS + j] - mx);
                sS[r * QS + j] = p;
                su += p;
            }
            sm_l[r] = sm_l[r] * al + su;
            sm_m[r] = mx;
            sm_a[r] = al;
        }
        __syncthreads();

        float al[4];
#pragma unroll
        for (int i = 0; i < 4; i++) al[i] = sm_a[q0 + i];
#pragma unroll
        for (int i = 0; i < 4; i++)
#pragma unroll
            for (int j = 0; j < 4; j++) acc[i][j] *= al[i];
#pragma unroll 8
        for (int kk = 0; kk < 64; kk++) {
            float p0 = sS[(q0 + 0) * QS + kk];
            float p1 = sS[(q0 + 1) * QS + kk];
            float p2 = sS[(q0 + 2) * QS + kk];
            float p3 = sS[(q0 + 3) * QS + kk];
            float v0 = sV[kk * QS + d0 + 0];
            float v1 = sV[kk * QS + d0 + 1];
            float v2 = sV[kk * QS + d0 + 2];
            float v3 = sV[kk * QS + d0 + 3];
            acc[0][0] += p0 * v0; acc[0][1] += p0 * v1; acc[0][2] += p0 * v2; acc[0][3] += p0 * v3;
            acc[1][0] += p1 * v0; acc[1][1] += p1 * v1; acc[1][2] += p1 * v2; acc[1][3] += p1 * v3;
            acc[2][0] += p2 * v0; acc[2][1] += p2 * v1; acc[2][2] += p2 * v2; acc[2][3] += p2 * v3;
            acc[3][0] += p3 * v0; acc[3][1] += p3 * v1; acc[3][2] += p3 * v2; acc[3][3] += p3 * v3;
        }
    }

    float linv[4];
#pragma unroll
    for (int i = 0; i < 4; i++) linv[i] = 1.0f / sm_l[q0 + i];
    float* op = out + (size_t)(b * TT + qb) * DM + h * HSZ;
#pragma unroll
    for (int i = 0; i < 4; i++)
#pragma unroll
        for (int j = 0; j < 4; j++)
            op[(size_t)(q0 + i) * DM + d0 + j] = acc[i][j] * linv[i];
}

// ---------------------------------------------------------------------------
__global__ void zero_kernel(float* red) { red[0] = 0.f; red[1] = 0.f; }

__global__ void loss_kernel(const float* __restrict__ logits, const int* __restrict__ tgt,
                            float* __restrict__ red) {
    int r = blockIdx.x;
    int tid = threadIdx.x;
    int warp = tid >> 5, lane = tid & 31;
    const float* row = logits + (size_t)r * VOC;
    __shared__ float rbuf[8];

    float lmax = -INFINITY;
    for (int c = tid; c < VOC; c += 256) lmax = fmaxf(lmax, row[c]);
    lmax = warpMax(lmax);
    if (lane == 0) rbuf[warp] = lmax;
    __syncthreads();
    float gmax = -INFINITY;
#pragma unroll
    for (int w = 0; w < 8; w++) gmax = fmaxf(gmax, rbuf[w]);
    __syncthreads();

    float lsum = 0.f;
    for (int c = tid; c < VOC; c += 256) lsum += expf(row[c] - gmax);
    lsum = warpSum(lsum);
    if (lane == 0) rbuf[warp] = lsum;
    __syncthreads();
    if (tid == 0) {
        float gsum = 0.f;
#pragma unroll
        for (int w = 0; w < 8; w++) gsum += rbuf[w];
        int tg = tgt[r];
        float lp = row[tg] - gmax - logf(gsum);
        float m = (tg != 0) ? 1.0f : 0.0f;
        atomicAdd(&red[0], -lp * m);
        atomicAdd(&red[1], m);
    }
}

__global__ void finalize_kernel(const float* __restrict__ red, float* __restrict__ outp) {
    outp[0] = red[0] / red[1];
}

// ---------------------------------------------------------------------------
extern "C" void kernel_launch(void* const* d_in, const int* in_sizes, int n_in,
                              void* d_out, int out_size) {
    const int*   toks = (const int*)d_in[0];
    const int*   tgts = (const int*)d_in[1];
    const float* temb = (const float*)d_in[2];
    const float* pemb = (const float*)d_in[3];
    const float* Wq   = (const float*)d_in[4];
    const float* Wk   = (const float*)d_in[5];
    const float* Wv   = (const float*)d_in[6];
    const float* Wo   = (const float*)d_in[7];
    const float* bo   = (const float*)d_in[8];
    const float* ln1g = (const float*)d_in[9];
    const float* ln1b = (const float*)d_in[10];
    const float* ln2g = (const float*)d_in[11];
    const float* ln2b = (const float*)d_in[12];
    const float* W1   = (const float*)d_in[13];
    const float* b1   = (const float*)d_in[14];
    const float* W2   = (const float*)d_in[15];
    const float* b2   = (const float*)d_in[16];
    const float* lnfg = (const float*)d_in[17];
    const float* lnfb = (const float*)d_in[18];
    const float* Wout = (const float*)d_in[19];
    const float* bout = (const float*)d_in[20];

    float *x, *h, *q, *k, *v, *a, *ff, *red, *lfb;
    cudaGetSymbolAddress((void**)&x,   g_x);
    cudaGetSymbolAddress((void**)&h,   g_h);
    cudaGetSymbolAddress((void**)&q,   g_q);
    cudaGetSymbolAddress((void**)&k,   g_k);
    cudaGetSymbolAddress((void**)&v,   g_v);
    cudaGetSymbolAddress((void**)&a,   g_a);
    cudaGetSymbolAddress((void**)&ff,  g_ff);
    cudaGetSymbolAddress((void**)&red, g_red);
    cudaGetSymbolAddress((void**)&lfb, g_logits_fb);

    cudaFuncSetAttribute(tgemm<0,0,0>, cudaFuncAttributeMaxDynamicSharedMemorySize, GEMM_SMEM);
    cudaFuncSetAttribute(tgemm<1,1,0>, cudaFuncAttributeMaxDynamicSharedMemorySize, GEMM_SMEM);
    cudaFuncSetAttribute(tgemm<1,0,1>, cudaFuncAttributeMaxDynamicSharedMemorySize, GEMM_SMEM);
    cudaFuncSetAttribute(tgemm<1,0,0>, cudaFuncAttributeMaxDynamicSharedMemorySize, GEMM_SMEM);
    cudaFuncSetAttribute(flash_attn,   cudaFuncAttributeMaxDynamicSharedMemorySize, FLASH_SMEM);

    embed_kernel<<<(NTOK * DM / 4 + 255) / 256, 256>>>(toks, temb, pemb, x);

    for (int l = 0; l < NL; l++) {
        ln_kernel<<<NTOK, 128>>>(x, h, ln1g + l * DM, ln1b + l * DM);

        tgemm<0,0,0><<<dim3(1, NTOK / 128, NH), 256, GEMM_SMEM>>>(
            h, Wq + (size_t)l * NH * DM * HSZ, nullptr, nullptr, q,
            NTOK, HSZ, DM, DM, HSZ, DM, (long)DM * HSZ, HSZ);
        tgemm<0,0,0><<<dim3(1, NTOK / 128, NH), 256, GEMM_SMEM>>>(
            h, Wk + (size_t)l * NH * DM * HSZ, nullptr, nullptr, k,
            NTOK, HSZ, DM, DM, HSZ, DM, (long)DM * HSZ, HSZ);
        tgemm<0,0,0><<<dim3(1, NTOK / 128, NH), 256, GEMM_SMEM>>>(
            h, Wv + (size_t)l * NH * DM * HSZ, nullptr, nullptr, v,
            NTOK, HSZ, DM, DM, HSZ, DM, (long)DM * HSZ, HSZ);

        flash_attn<<<dim3(TT / 64, NH, BT), 256, FLASH_SMEM>>>(q, k, v, a);

        tgemm<1,1,0><<<dim3(DM / 64, NTOK / 128, 1), 256, GEMM_SMEM>>>(
            a, Wo + (size_t)l * DM * DM, bo + l * DM, x, x,
            NTOK, DM, DM, DM, DM, DM, 0, 0);

        ln_kernel<<<NTOK, 128>>>(x, h, ln2g + l * DM, ln2b + l * DM);

        tgemm<1,0,1><<<dim3(FFD / 64, NTOK / 128, 1), 256, GEMM_SMEM>>>(
            h, W1 + (size_t)l * DM * FFD, b1 + (size_t)l * FFD, nullptr, ff,
            NTOK, FFD, DM, DM, FFD, FFD, 0, 0);
        tgemm<1,1,0><<<dim3(DM / 64, NTOK / 128, 1), 256, GEMM_SMEM>>>(
            ff, W2 + (size_t)l * FFD * DM, b2 + l * DM, x, x,
            NTOK, DM, FFD, FFD, DM, DM, 0, 0);
    }

    ln_kernel<<<NTOK, 128>>>(x, h, lnfg, lnfb);

    const long logitsElems = (long)NTOK * VOC;
    float* logits = ((long)out_size >= logitsElems) ? (float*)d_out : lfb;

    tgemm<1,0,0><<<dim3(VOC / 64, NTOK / 128, 1), 256, GEMM_SMEM>>>(
        h, Wout, bout, nullptr, logits,
        NTOK, VOC, DM, DM, VOC, VOC, 0, 0);

    if ((long)out_size != logitsElems) {
        zero_kernel<<<1, 1>>>(red);
        loss_kernel<<<NTOK, 256>>>(logits, tgts, red);
        float* lossOut;
        if ((long)out_size > logitsElems)
            lossOut = (float*)d_out + logitsElems;
        else
            lossOut = (float*)d_out + (out_size - 1);
        finalize_kernel<<<1, 1>>>(red, lossOut);
    }
}